// round 11
// baseline (speedup 1.0000x reference)
#include <cuda_runtime.h>

#define HDIM 1024
#define LSEQ 512
#define G4   4096      // 4*H gate rows
#define KIN  4096      // input feature dim (2H + 2H)
#define NLAB 122
#define RGRID 128      // recurrent kernel CTAs (<=148: one wave, persistent-safe)
#define PGRID 148      // pregemm persistent CTAs: exactly one per SM
#define NTILES ((LSEQ / 64) * (G4 / 64))   // 8 * 64 = 512 tiles

#define SENTINEL 0x7FC00001u   // NaN payload; computed values are never NaN

// ---------------- scratch (no allocation allowed; device globals) -------------
__device__ __align__(256) float g_Wcomb[G4 * HDIM];   // W_ih[:,4096:] + W_hh
__device__ __align__(256) float g_bias[G4];           // b_ih + b_hh
__device__ __align__(256) float g_Xpre[LSEQ * G4];    // input projection + bias
__device__ __align__(256) float g_outs[LSEQ * HDIM];  // h_t for all steps

// ---------------- L2-coherent load/store helpers ------------------------------
__device__ __forceinline__ float4 ldcg4(const float4* p) {
    float4 v;
    asm volatile("ld.global.cg.v4.f32 {%0,%1,%2,%3}, [%4];"
                 : "=f"(v.x), "=f"(v.y), "=f"(v.z), "=f"(v.w) : "l"(p));
    return v;
}
__device__ __forceinline__ float ldcg1(const float* p) {
    float v;
    asm volatile("ld.global.cg.f32 %0, [%1];" : "=f"(v) : "l"(p));
    return v;
}
__device__ __forceinline__ void stcg(float* p, float v) {
    asm volatile("st.global.cg.f32 [%0], %1;" :: "l"(p), "f"(v));
}
__device__ __forceinline__ bool has_sentinel(float4 v) {
    return (__float_as_uint(v.x) == SENTINEL) | (__float_as_uint(v.y) == SENTINEL) |
           (__float_as_uint(v.z) == SENTINEL) | (__float_as_uint(v.w) == SENTINEL);
}
// Spin only if the prefetched value was still a sentinel.
__device__ __forceinline__ float revalidate(float v, const float* p) {
    while (__float_as_uint(v) == SENTINEL) { __nanosleep(32); v = ldcg1(p); }
    return v;
}

// ---------------- prep: fold weights/biases, poison Xpre + h buffers ----------
__global__ void prep_kernel(const float* __restrict__ W_ih,
                            const float* __restrict__ W_hh,
                            const float* __restrict__ b_ih,
                            const float* __restrict__ b_hh) {
    int idx = blockIdx.x * blockDim.x + threadIdx.x;
    if (idx < G4 * HDIM) {
        int r = idx >> 10;           // gate row
        int c = idx & 1023;          // h col
        g_Wcomb[idx] = W_ih[(size_t)r * 5120 + 4096 + c] + W_hh[idx];
    }
    if (idx < G4) g_bias[idx] = b_ih[idx] + b_hh[idx];
    if (idx < LSEQ * G4)  g_Xpre[idx] = __uint_as_float(SENTINEL);
    if (idx < LSEQ * HDIM) g_outs[idx] = __uint_as_float(SENTINEL);
}

// ---------------- pregemm: PERSISTENT, one slim CTA per SM --------------------
// 148 CTAs x 128 thr (~80 regs, 9KB smem) grid-stride over 512 64x64 tiles in
// t-major order (tiles 0..63 = timesteps 0..63). Launched FIRST (it never
// waits => safe under ncu kernel serialization); one CTA per SM leaves ~54K
// registers free so a fat recur CTA co-resides on every SM from the start and
// the GEMM fills the recurrence's idle issue slots.
__global__ __launch_bounds__(128) void pregemm_kernel(
    const float* __restrict__ x, const float* __restrict__ hi,
    const float* __restrict__ W_ih) {
    __shared__ __align__(16) float As[16][68];   // [k][t]
    __shared__ __align__(16) float Bs[16][68];   // [k][n]

    const int tid = threadIdx.x;
    const int tm = tid & 15;          // 16 m-groups of 4 rows
    const int tn = tid >> 4;          // 8 n-groups of 8 cols

    for (int tile = blockIdx.x; tile < NTILES; tile += PGRID) {
        const int bt = (tile >> 6) * 64;   // t-major: early timesteps first
        const int bn = (tile & 63) * 64;

        float acc[4][8];
#pragma unroll
        for (int i = 0; i < 4; i++)
#pragma unroll
            for (int j = 0; j < 8; j++) acc[i][j] = 0.f;

        for (int k0 = 0; k0 < KIN; k0 += 16) {
            // A tile: 64 t-rows x 16 k = 256 float4, 128 thr -> 2 each.
            // float4 never straddles the x/hi boundary (2048 % 16 == 0).
#pragma unroll
            for (int it = 0; it < 2; it++) {
                int idx = tid + it * 128;
                int m = idx >> 2;
                int kq = idx & 3;
                int gk = k0 + kq * 4;
                float4 v;
                if (gk < 2048)
                    v = *(const float4*)(x + (size_t)(bt + m) * 2048 + gk);
                else
                    v = *(const float4*)(hi + (size_t)(bt + m) * 2048 + gk - 2048);
                As[kq * 4 + 0][m] = v.x;
                As[kq * 4 + 1][m] = v.y;
                As[kq * 4 + 2][m] = v.z;
                As[kq * 4 + 3][m] = v.w;
            }
            // B tile: 64 gate rows x 16 k (W_ih row stride 5120 floats)
#pragma unroll
            for (int it = 0; it < 2; it++) {
                int idx = tid + it * 128;
                int n = idx >> 2;
                int kq = idx & 3;
                float4 v = *(const float4*)(W_ih + (size_t)(bn + n) * 5120 + k0 + kq * 4);
                Bs[kq * 4 + 0][n] = v.x;
                Bs[kq * 4 + 1][n] = v.y;
                Bs[kq * 4 + 2][n] = v.z;
                Bs[kq * 4 + 3][n] = v.w;
            }
            __syncthreads();
#pragma unroll
            for (int k = 0; k < 16; k++) {
                float4 a4 = *(const float4*)&As[k][tm * 4];
                float4 b0 = *(const float4*)&Bs[k][tn * 8];
                float4 b1 = *(const float4*)&Bs[k][tn * 8 + 4];
                float a[4] = {a4.x, a4.y, a4.z, a4.w};
                float b[8] = {b0.x, b0.y, b0.z, b0.w, b1.x, b1.y, b1.z, b1.w};
#pragma unroll
                for (int i = 0; i < 4; i++)
#pragma unroll
                    for (int j = 0; j < 8; j++) acc[i][j] += a[i] * b[j];
            }
            __syncthreads();
        }
        // Epilogue: add bias, st.cg so polling recur CTAs see values in L2.
#pragma unroll
        for (int j = 0; j < 8; j++) {
            int n = bn + tn * 8 + j;
            float bb = g_bias[n];
#pragma unroll
            for (int i = 0; i < 4; i++) {
                int m = bt + tm * 4 + i;
                stcg(g_Xpre + (size_t)m * G4 + n, acc[i][j] + bb);
            }
        }
        // smem safe to reuse: last __syncthreads() in k-loop ordered all reads.
    }
}

// ---------------- recurrent persistent kernel --------------------------------
// Data-driven sync: g_Xpre (from the concurrent pregemm) and g_outs (from peer
// CTAs) are sentinel-poisoned; consumers poll values directly. Xpre is
// prefetched non-blocking at step top and validated (spun on) only at the gate
// computation, giving the producer the FMA+reduce latency as slack.
__device__ __forceinline__ float fast_sigmoid(float v) {
    return 1.f / (1.f + __expf(-v));
}
__device__ __forceinline__ float fast_tanh(float v) {
    v = fminf(fmaxf(v, -15.f), 15.f);
    float e = __expf(-2.f * v);
    return (1.f - e) / (1.f + e);
}

__global__ __launch_bounds__(256, 1) void recur_kernel() {
    __shared__ __align__(16) float h_s[HDIM];
    const int tid  = threadIdx.x;
    const int lane = tid & 31;
    const int warp = tid >> 5;                 // 0..7
    const int j    = blockIdx.x * 8 + warp;    // h element, 0..1023

    // This warp's 4 gate rows of W_comb live in registers.
    float w[4][32];
#pragma unroll
    for (int g = 0; g < 4; g++) {
        const float* base = g_Wcomb + (size_t)(j + g * HDIM) * HDIM;
#pragma unroll
        for (int k = 0; k < 32; k++) w[g][k] = base[k * 32 + lane];
    }

    float c_state = 0.f;    // meaningful on lane 0 only

    for (int t = 0; t < LSEQ; t++) {
        // Non-blocking prefetch of the gate pre-activations (validated later).
        float xi = 0.f, xf = 0.f, xg = 0.f, xo = 0.f;
        const float* xp = g_Xpre + (size_t)t * G4;
        if (lane == 0) {
            xi = ldcg1(xp + j);
            xf = ldcg1(xp + j + 1024);
            xg = ldcg1(xp + j + 2048);
            xo = ldcg1(xp + j + 3072);
        }

        // Stage h_{t-1}: poll the values themselves until non-sentinel.
        if (t == 0) {
            ((float4*)h_s)[tid] = make_float4(0.f, 0.f, 0.f, 0.f);
        } else {
            const float4* hp4 = (const float4*)(g_outs + (size_t)(t - 1) * HDIM);
            float4 v = ldcg4(hp4 + tid);
            while (has_sentinel(v)) {
                __nanosleep(32);
                v = ldcg4(hp4 + tid);
            }
            ((float4*)h_s)[tid] = v;
        }
        __syncthreads();

        float a0 = 0.f, a1 = 0.f, a2 = 0.f, a3 = 0.f;
#pragma unroll
        for (int k = 0; k < 32; k++) {
            float hv = h_s[k * 32 + lane];
            a0 += w[0][k] * hv;
            a1 += w[1][k] * hv;
            a2 += w[2][k] * hv;
            a3 += w[3][k] * hv;
        }
#pragma unroll
        for (int off = 16; off > 0; off >>= 1) {
            a0 += __shfl_down_sync(0xffffffffu, a0, off);
            a1 += __shfl_down_sync(0xffffffffu, a1, off);
            a2 += __shfl_down_sync(0xffffffffu, a2, off);
            a3 += __shfl_down_sync(0xffffffffu, a3, off);
        }
        if (lane == 0) {
            // Validate the prefetch; spin only if pregemm hasn't produced yet.
            xi = revalidate(xi, xp + j);
            xf = revalidate(xf, xp + j + 1024);
            xg = revalidate(xg, xp + j + 2048);
            xo = revalidate(xo, xp + j + 3072);
            float gi = xi + a0;
            float gf = xf + a1;
            float gg = xg + a2;
            float go = xo + a3;
            float si = fast_sigmoid(gi);
            float sf = fast_sigmoid(gf);
            float so = fast_sigmoid(go);
            c_state = sf * c_state + si * fast_tanh(gg);
            // This store is the release: consumers poll this exact location.
            stcg(g_outs + (size_t)t * HDIM + j, so * fast_tanh(c_state));
        }
        __syncthreads();   // protect h_s reuse next iteration
    }
}

// ---------------- final FC: out[t][l] = b_fc[l] + outs[t] . W_fc[l] ----------
__global__ __launch_bounds__(256) void fc_kernel(const float* __restrict__ W_fc,
                                                 const float* __restrict__ b_fc,
                                                 float* __restrict__ out) {
    __shared__ __align__(16) float hs[4][HDIM];
    const int t0  = blockIdx.x * 4;
    const int tid = threadIdx.x;
    const int half = tid >> 7;          // 0 or 1
    const int l    = tid & 127;         // label index

    const float4* src = (const float4*)(g_outs + (size_t)t0 * HDIM);
    float4* dst = (float4*)hs;
#pragma unroll
    for (int i = tid; i < HDIM; i += 256) dst[i] = src[i];   // 1024 float4
    __syncthreads();

    if (l < NLAB) {
        const float4* wr = (const float4*)(W_fc + (size_t)l * HDIM);
        const float4* ha = (const float4*)hs[half * 2];
        const float4* hb = (const float4*)hs[half * 2 + 1];
        float s0 = 0.f, s1 = 0.f;
#pragma unroll 8
        for (int k = 0; k < HDIM / 4; k++) {
            float4 w = wr[k];
            float4 a = ha[k], b = hb[k];
            s0 += w.x * a.x + w.y * a.y + w.z * a.z + w.w * a.w;
            s1 += w.x * b.x + w.y * b.y + w.z * b.z + w.w * b.w;
        }
        float bb = b_fc[l];
        out[(size_t)(t0 + half * 2) * NLAB + l]     = s0 + bb;
        out[(size_t)(t0 + half * 2 + 1) * NLAB + l] = s1 + bb;
    }
}

// ---------------- launch ------------------------------------------------------
// Ordering rule: the dependency-free kernel (pregemm) launches FIRST. Under
// ncu's kernel serialization it completes standalone; recur then finds its
// inputs ready. In normal concurrent execution the 148 one-per-SM pregemm
// CTAs co-reside with recur's 128 fat CTAs and fill their idle issue slots.
extern "C" void kernel_launch(void* const* d_in, const int* in_sizes, int n_in,
                              void* d_out, int out_size) {
    const float* x    = (const float*)d_in[0];
    const float* hi   = (const float*)d_in[1];
    const float* W_ih = (const float*)d_in[2];
    const float* W_hh = (const float*)d_in[3];
    const float* b_ih = (const float*)d_in[4];
    const float* b_hh = (const float*)d_in[5];
    const float* W_fc = (const float*)d_in[6];
    const float* b_fc = (const float*)d_in[7];
    float* out = (float*)d_out;

    static cudaStream_t s2 = nullptr;
    static cudaEvent_t evA = nullptr, evB = nullptr;
    if (s2 == nullptr) {
        cudaStreamCreateWithFlags(&s2, cudaStreamNonBlocking);
        cudaEventCreateWithFlags(&evA, cudaEventDisableTiming);
        cudaEventCreateWithFlags(&evB, cudaEventDisableTiming);
    }

    prep_kernel<<<(G4 * HDIM + 255) / 256, 256>>>(W_ih, W_hh, b_ih, b_hh);

    // Fork after prep: pregemm (s2) first — it never waits — then recur.
    cudaEventRecord(evA, 0);
    cudaStreamWaitEvent(s2, evA, 0);

    pregemm_kernel<<<PGRID, 128, 0, s2>>>(x, hi, W_ih);
    cudaEventRecord(evB, s2);

    recur_kernel<<<RGRID, 256>>>();

    // Join before fc (fc reads g_outs; graph re-converges here).
    cudaStreamWaitEvent(0, evB, 0);
    fc_kernel<<<LSEQ / 4, 256>>>(W_fc, b_fc, out);
}

// round 13
// speedup vs baseline: 1.8096x; 1.8096x over previous
#include <cuda_runtime.h>

#define HDIM 1024
#define LSEQ 512
#define G4   4096      // 4*H gate rows
#define KIN  4096      // input feature dim (2H + 2H)
#define NLAB 122
#define RGRID 128      // recurrent kernel CTAs (<=148: one wave, persistent-safe)

#define SENTINEL 0x7FC00001u   // NaN payload; computed values are never NaN

// ---------------- scratch (no allocation allowed; device globals) -------------
__device__ __align__(256) float g_Wcomb[G4 * HDIM];   // W_ih[:,4096:] + W_hh
__device__ __align__(256) float g_bias[G4];           // b_ih + b_hh
__device__ __align__(256) float g_Xpre[LSEQ * G4];    // input projection + bias
__device__ __align__(256) float g_outs[LSEQ * HDIM];  // h_t for all steps

// ---------------- race-free signal helpers (relaxed GPU-scope atomics) --------
// Value-as-flag: the 32-bit value IS the payload, so relaxed is sufficient —
// no fences, no acquire/release, and the race is DEFINED (unlike plain ld/st).
__device__ __forceinline__ unsigned ldrx(const float* p) {
    unsigned v;
    asm volatile("ld.relaxed.gpu.global.b32 %0, [%1];" : "=r"(v) : "l"(p));
    return v;
}
__device__ __forceinline__ void strx(float* p, float v) {
    asm volatile("st.relaxed.gpu.global.b32 [%0], %1;"
                 :: "l"(p), "r"(__float_as_uint(v)));
}
// Cycle-granular backoff (no __nanosleep: its coarse quantum lands on the
// critical path of every step's first failed poll).
__device__ __forceinline__ void pause_cycles(unsigned long long n) {
    unsigned long long s = clock64();
    while (clock64() - s < n) { }
}
__device__ __forceinline__ float poll_value(const float* p) {
    unsigned v = ldrx(p);
    while (v == SENTINEL) { pause_cycles(200); v = ldrx(p); }
    return __uint_as_float(v);
}

// ---------------- prep: fold weights/biases, poison Xpre + h buffers ----------
__global__ void prep_kernel(const float* __restrict__ W_ih,
                            const float* __restrict__ W_hh,
                            const float* __restrict__ b_ih,
                            const float* __restrict__ b_hh) {
    int idx = blockIdx.x * blockDim.x + threadIdx.x;
    if (idx < G4 * HDIM) {
        int r = idx >> 10;           // gate row
        int c = idx & 1023;          // h col
        g_Wcomb[idx] = W_ih[(size_t)r * 5120 + 4096 + c] + W_hh[idx];
    }
    if (idx < G4) g_bias[idx] = b_ih[idx] + b_hh[idx];
    if (idx < LSEQ * G4)  g_Xpre[idx] = __uint_as_float(SENTINEL);
    if (idx < LSEQ * HDIM) g_outs[idx] = __uint_as_float(SENTINEL);
}

// ---------------- pregemm: 64x64x16 tiles, 512 slim CTAs (R6 config) ----------
__global__ __launch_bounds__(128) void pregemm_kernel(
    const float* __restrict__ x, const float* __restrict__ hi,
    const float* __restrict__ W_ih) {
    __shared__ __align__(16) float As[16][68];   // [k][t]
    __shared__ __align__(16) float Bs[16][68];   // [k][n]

    const int bn = blockIdx.x * 64;   // gate-row strip
    const int bt = blockIdx.y * 64;   // timestep block
    const int tid = threadIdx.x;
    const int tm = tid & 15;          // 16 m-groups of 4 rows
    const int tn = tid >> 4;          // 8 n-groups of 8 cols

    float acc[4][8];
#pragma unroll
    for (int i = 0; i < 4; i++)
#pragma unroll
        for (int j = 0; j < 8; j++) acc[i][j] = 0.f;

    for (int k0 = 0; k0 < KIN; k0 += 16) {
        // A tile: 64 t-rows x 16 k = 256 float4, 128 thr -> 2 each.
        // float4 never straddles the x/hi boundary (2048 % 16 == 0).
#pragma unroll
        for (int it = 0; it < 2; it++) {
            int idx = tid + it * 128;
            int m = idx >> 2;
            int kq = idx & 3;
            int gk = k0 + kq * 4;
            float4 v;
            if (gk < 2048)
                v = *(const float4*)(x + (size_t)(bt + m) * 2048 + gk);
            else
                v = *(const float4*)(hi + (size_t)(bt + m) * 2048 + gk - 2048);
            As[kq * 4 + 0][m] = v.x;
            As[kq * 4 + 1][m] = v.y;
            As[kq * 4 + 2][m] = v.z;
            As[kq * 4 + 3][m] = v.w;
        }
        // B tile: 64 gate rows x 16 k (W_ih row stride 5120 floats)
#pragma unroll
        for (int it = 0; it < 2; it++) {
            int idx = tid + it * 128;
            int n = idx >> 2;
            int kq = idx & 3;
            float4 v = *(const float4*)(W_ih + (size_t)(bn + n) * 5120 + k0 + kq * 4);
            Bs[kq * 4 + 0][n] = v.x;
            Bs[kq * 4 + 1][n] = v.y;
            Bs[kq * 4 + 2][n] = v.z;
            Bs[kq * 4 + 3][n] = v.w;
        }
        __syncthreads();
#pragma unroll
        for (int k = 0; k < 16; k++) {
            float4 a4 = *(const float4*)&As[k][tm * 4];
            float4 b0 = *(const float4*)&Bs[k][tn * 8];
            float4 b1 = *(const float4*)&Bs[k][tn * 8 + 4];
            float a[4] = {a4.x, a4.y, a4.z, a4.w};
            float b[8] = {b0.x, b0.y, b0.z, b0.w, b1.x, b1.y, b1.z, b1.w};
#pragma unroll
            for (int i = 0; i < 4; i++)
#pragma unroll
                for (int j = 0; j < 8; j++) acc[i][j] += a[i] * b[j];
        }
        __syncthreads();
    }
    // Epilogue: add bias; relaxed stores so polling consumers read race-free.
#pragma unroll
    for (int j = 0; j < 8; j++) {
        int n = bn + tn * 8 + j;
        float bb = g_bias[n];
#pragma unroll
        for (int i = 0; i < 4; i++) {
            int m = bt + tm * 4 + i;
            strx(g_Xpre + (size_t)m * G4 + n, acc[i][j] + bb);
        }
    }
}

// ---------------- recurrent persistent kernel --------------------------------
// Data-driven sync: g_Xpre and g_outs are sentinel-poisoned; consumers poll
// the values with relaxed atomics and cycle-granular backoff.
__device__ __forceinline__ float fast_sigmoid(float v) {
    return 1.f / (1.f + __expf(-v));
}
__device__ __forceinline__ float fast_tanh(float v) {
    v = fminf(fmaxf(v, -15.f), 15.f);
    float e = __expf(-2.f * v);
    return (1.f - e) / (1.f + e);
}

__global__ __launch_bounds__(256, 1) void recur_kernel() {
    __shared__ __align__(16) float h_s[HDIM];
    const int tid  = threadIdx.x;
    const int lane = tid & 31;
    const int warp = tid >> 5;                 // 0..7
    const int j    = blockIdx.x * 8 + warp;    // h element, 0..1023

    // This warp's 4 gate rows of W_comb live in registers.
    float w[4][32];
#pragma unroll
    for (int g = 0; g < 4; g++) {
        const float* base = g_Wcomb + (size_t)(j + g * HDIM) * HDIM;
#pragma unroll
        for (int k = 0; k < 32; k++) w[g][k] = base[k * 32 + lane];
    }

    float c_state = 0.f;    // meaningful on lane 0 only

    for (int t = 0; t < LSEQ; t++) {
        // Gate pre-activations from pregemm (usually ready; poll if not).
        float xi = 0.f, xf = 0.f, xg = 0.f, xo = 0.f;
        const float* xp = g_Xpre + (size_t)t * G4;
        if (lane == 0) {
            xi = poll_value(xp + j);
            xf = poll_value(xp + j + 1024);
            xg = poll_value(xp + j + 2048);
            xo = poll_value(xp + j + 3072);
        }

        // Stage h_{t-1}: each thread polls its 4 elements (race-free relaxed).
        if (t == 0) {
            ((float4*)h_s)[tid] = make_float4(0.f, 0.f, 0.f, 0.f);
        } else {
            const float* hp = g_outs + (size_t)(t - 1) * HDIM + tid * 4;
            float4 v;
            v.x = poll_value(hp + 0);
            v.y = poll_value(hp + 1);
            v.z = poll_value(hp + 2);
            v.w = poll_value(hp + 3);
            ((float4*)h_s)[tid] = v;
        }
        __syncthreads();

        float a0 = 0.f, a1 = 0.f, a2 = 0.f, a3 = 0.f;
#pragma unroll
        for (int k = 0; k < 32; k++) {
            float hv = h_s[k * 32 + lane];
            a0 += w[0][k] * hv;
            a1 += w[1][k] * hv;
            a2 += w[2][k] * hv;
            a3 += w[3][k] * hv;
        }
#pragma unroll
        for (int off = 16; off > 0; off >>= 1) {
            a0 += __shfl_down_sync(0xffffffffu, a0, off);
            a1 += __shfl_down_sync(0xffffffffu, a1, off);
            a2 += __shfl_down_sync(0xffffffffu, a2, off);
            a3 += __shfl_down_sync(0xffffffffu, a3, off);
        }
        if (lane == 0) {
            float gi = xi + a0;
            float gf = xf + a1;
            float gg = xg + a2;
            float go = xo + a3;
            float si = fast_sigmoid(gi);
            float sf = fast_sigmoid(gf);
            float so = fast_sigmoid(go);
            c_state = sf * c_state + si * fast_tanh(gg);
            // Relaxed store is the release: consumers poll this location.
            strx(g_outs + (size_t)t * HDIM + j, so * fast_tanh(c_state));
        }
        __syncthreads();   // protect h_s reuse next iteration
    }
}

// ---------------- final FC: out[t][l] = b_fc[l] + outs[t] . W_fc[l] ----------
__global__ __launch_bounds__(256) void fc_kernel(const float* __restrict__ W_fc,
                                                 const float* __restrict__ b_fc,
                                                 float* __restrict__ out) {
    __shared__ __align__(16) float hs[4][HDIM];
    const int t0  = blockIdx.x * 4;
    const int tid = threadIdx.x;
    const int half = tid >> 7;          // 0 or 1
    const int l    = tid & 127;         // label index

    const float4* src = (const float4*)(g_outs + (size_t)t0 * HDIM);
    float4* dst = (float4*)hs;
#pragma unroll
    for (int i = tid; i < HDIM; i += 256) dst[i] = src[i];   // 1024 float4
    __syncthreads();

    if (l < NLAB) {
        const float4* wr = (const float4*)(W_fc + (size_t)l * HDIM);
        const float4* ha = (const float4*)hs[half * 2];
        const float4* hb = (const float4*)hs[half * 2 + 1];
        float s0 = 0.f, s1 = 0.f;
#pragma unroll 8
        for (int k = 0; k < HDIM / 4; k++) {
            float4 w = wr[k];
            float4 a = ha[k], b = hb[k];
            s0 += w.x * a.x + w.y * a.y + w.z * a.z + w.w * a.w;
            s1 += w.x * b.x + w.y * b.y + w.z * b.z + w.w * b.w;
        }
        float bb = b_fc[l];
        out[(size_t)(t0 + half * 2) * NLAB + l]     = s0 + bb;
        out[(size_t)(t0 + half * 2 + 1) * NLAB + l] = s1 + bb;
    }
}

// ---------------- launch (R6 ordering: dependency-free pregemm first) ---------
extern "C" void kernel_launch(void* const* d_in, const int* in_sizes, int n_in,
                              void* d_out, int out_size) {
    const float* x    = (const float*)d_in[0];
    const float* hi   = (const float*)d_in[1];
    const float* W_ih = (const float*)d_in[2];
    const float* W_hh = (const float*)d_in[3];
    const float* b_ih = (const float*)d_in[4];
    const float* b_hh = (const float*)d_in[5];
    const float* W_fc = (const float*)d_in[6];
    const float* b_fc = (const float*)d_in[7];
    float* out = (float*)d_out;

    static cudaStream_t s2 = nullptr;
    static cudaEvent_t evA = nullptr, evB = nullptr;
    if (s2 == nullptr) {
        cudaStreamCreateWithFlags(&s2, cudaStreamNonBlocking);
        cudaEventCreateWithFlags(&evA, cudaEventDisableTiming);
        cudaEventCreateWithFlags(&evB, cudaEventDisableTiming);
    }

    prep_kernel<<<(G4 * HDIM + 255) / 256, 256>>>(W_ih, W_hh, b_ih, b_hh);

    // Fork after prep: pregemm on s2 (never waits on anything), then recur.
    cudaEventRecord(evA, 0);
    cudaStreamWaitEvent(s2, evA, 0);

    dim3 pgrid(64, 8);   // 64 n-strips x 8 t-blocks
    pregemm_kernel<<<pgrid, 128, 0, s2>>>(x, hi, W_ih);
    cudaEventRecord(evB, s2);

    recur_kernel<<<RGRID, 256>>>();

    // Join before fc (fc reads g_outs; graph re-converges here).
    cudaStreamWaitEvent(0, evB, 0);
    fc_kernel<<<LSEQ / 4, 256>>>(W_fc, b_fc, out);
}

// round 14
// speedup vs baseline: 2.0894x; 1.1546x over previous
#include <cuda_runtime.h>

#define HDIM 1024
#define LSEQ 512
#define G4   4096      // 4*H gate rows
#define KIN  4096      // input feature dim (2H + 2H)
#define NLAB 122
#define RGRID 128      // recurrent kernel CTAs (<=148: one wave, persistent-safe)

#define SENTINEL 0x7FC00001u   // NaN payload; computed values are never NaN

typedef unsigned long long u64;

// ---------------- packed f32x2 helpers (FFMA2 path, sm_103a) ------------------
__device__ __forceinline__ u64 pack2(float lo, float hi) {
    u64 r; asm("mov.b64 %0, {%1, %2};" : "=l"(r) : "f"(lo), "f"(hi)); return r;
}
__device__ __forceinline__ void unpack2(u64 v, float& lo, float& hi) {
    asm("mov.b64 {%0, %1}, %2;" : "=f"(lo), "=f"(hi) : "l"(v));
}
__device__ __forceinline__ u64 fma2(u64 a, u64 b, u64 c) {
    u64 d; asm("fma.rn.f32x2 %0, %1, %2, %3;" : "=l"(d) : "l"(a), "l"(b), "l"(c));
    return d;
}

// ---------------- scratch (no allocation allowed; device globals) -------------
__device__ __align__(256) float g_Wcomb[G4 * HDIM];   // W_ih[:,4096:] + W_hh
__device__ __align__(256) float g_bias[G4];           // b_ih + b_hh
__device__ __align__(256) float g_Xpre[LSEQ * G4];    // input projection + bias
__device__ __align__(256) float g_outs[LSEQ * HDIM];  // h_t for all steps

// ---------------- L2-coherent load/store helpers (R6-proven) ------------------
__device__ __forceinline__ float4 ldcg4(const float4* p) {
    float4 v;
    asm volatile("ld.global.cg.v4.f32 {%0,%1,%2,%3}, [%4];"
                 : "=f"(v.x), "=f"(v.y), "=f"(v.z), "=f"(v.w) : "l"(p));
    return v;
}
__device__ __forceinline__ float ldcg1(const float* p) {
    float v;
    asm volatile("ld.global.cg.f32 %0, [%1];" : "=f"(v) : "l"(p));
    return v;
}
__device__ __forceinline__ void stcg(float* p, float v) {
    asm volatile("st.global.cg.f32 [%0], %1;" :: "l"(p), "f"(v));
}
__device__ __forceinline__ bool has_sentinel(float4 v) {
    return (__float_as_uint(v.x) == SENTINEL) | (__float_as_uint(v.y) == SENTINEL) |
           (__float_as_uint(v.z) == SENTINEL) | (__float_as_uint(v.w) == SENTINEL);
}
__device__ __forceinline__ float poll_scalar(const float* p) {
    float v = ldcg1(p);
    while (__float_as_uint(v) == SENTINEL) { __nanosleep(64); v = ldcg1(p); }
    return v;
}

// ---------------- prep: fold weights/biases, poison Xpre + h buffers ----------
__global__ void prep_kernel(const float* __restrict__ W_ih,
                            const float* __restrict__ W_hh,
                            const float* __restrict__ b_ih,
                            const float* __restrict__ b_hh) {
    int idx = blockIdx.x * blockDim.x + threadIdx.x;
    if (idx < G4 * HDIM) {
        int r = idx >> 10;           // gate row
        int c = idx & 1023;          // h col
        g_Wcomb[idx] = W_ih[(size_t)r * 5120 + 4096 + c] + W_hh[idx];
    }
    if (idx < G4) g_bias[idx] = b_ih[idx] + b_hh[idx];
    if (idx < LSEQ * G4)  g_Xpre[idx] = __uint_as_float(SENTINEL);
    if (idx < LSEQ * HDIM) g_outs[idx] = __uint_as_float(SENTINEL);
}

// ---------------- pregemm: 64x64x16 tiles, 512 slim CTAs (R6 config) ----------
// Inner loop switched to packed FFMA2 (R4-proven numerics: acc order per
// output element unchanged). 128 thr, low regs => backfills behind recur.
__global__ __launch_bounds__(128) void pregemm_kernel(
    const float* __restrict__ x, const float* __restrict__ hi,
    const float* __restrict__ W_ih) {
    __shared__ __align__(16) float As[16][68];   // [k][t]
    __shared__ __align__(16) float Bs[16][68];   // [k][n]

    const int bn = blockIdx.x * 64;   // gate-row strip
    const int bt = blockIdx.y * 64;   // timestep block
    const int tid = threadIdx.x;
    const int tm = tid & 15;          // 16 m-groups of 4 rows
    const int tn = tid >> 4;          // 8 n-groups of 8 cols

    u64 acc2[2][8];                    // packed over the m dimension (4 rows->2)
#pragma unroll
    for (int i = 0; i < 2; i++)
#pragma unroll
        for (int j = 0; j < 8; j++) acc2[i][j] = pack2(0.f, 0.f);

    for (int k0 = 0; k0 < KIN; k0 += 16) {
        // A tile: 64 t-rows x 16 k = 256 float4, 128 thr -> 2 each.
        // float4 never straddles the x/hi boundary (2048 % 16 == 0).
#pragma unroll
        for (int it = 0; it < 2; it++) {
            int idx = tid + it * 128;
            int m = idx >> 2;
            int kq = idx & 3;
            int gk = k0 + kq * 4;
            float4 v;
            if (gk < 2048)
                v = *(const float4*)(x + (size_t)(bt + m) * 2048 + gk);
            else
                v = *(const float4*)(hi + (size_t)(bt + m) * 2048 + gk - 2048);
            As[kq * 4 + 0][m] = v.x;
            As[kq * 4 + 1][m] = v.y;
            As[kq * 4 + 2][m] = v.z;
            As[kq * 4 + 3][m] = v.w;
        }
        // B tile: 64 gate rows x 16 k (W_ih row stride 5120 floats)
#pragma unroll
        for (int it = 0; it < 2; it++) {
            int idx = tid + it * 128;
            int n = idx >> 2;
            int kq = idx & 3;
            float4 v = *(const float4*)(W_ih + (size_t)(bn + n) * 5120 + k0 + kq * 4);
            Bs[kq * 4 + 0][n] = v.x;
            Bs[kq * 4 + 1][n] = v.y;
            Bs[kq * 4 + 2][n] = v.z;
            Bs[kq * 4 + 3][n] = v.w;
        }
        __syncthreads();
#pragma unroll
        for (int k = 0; k < 16; k++) {
            u64 a2[2];
            a2[0] = *(const u64*)&As[k][tm * 4];
            a2[1] = *(const u64*)&As[k][tm * 4 + 2];
            u64 b2[8];
#pragma unroll
            for (int j = 0; j < 8; j++) {
                float bv = Bs[k][tn * 8 + j];
                b2[j] = pack2(bv, bv);
            }
#pragma unroll
            for (int i = 0; i < 2; i++)
#pragma unroll
                for (int j = 0; j < 8; j++)
                    acc2[i][j] = fma2(a2[i], b2[j], acc2[i][j]);
        }
        __syncthreads();
    }
    // Epilogue: add bias; st.cg so polling recur CTAs see values in L2.
#pragma unroll
    for (int i = 0; i < 2; i++) {
#pragma unroll
        for (int j = 0; j < 8; j++) {
            int n = bn + tn * 8 + j;
            float lo, hh;
            unpack2(acc2[i][j], lo, hh);
            int m0 = bt + tm * 4 + 2 * i;
            float bb = g_bias[n];
            stcg(g_Xpre + (size_t)m0 * G4 + n,       lo + bb);
            stcg(g_Xpre + (size_t)(m0 + 1) * G4 + n, hh + bb);
        }
    }
}

// ---------------- recurrent persistent kernel (R6 sync, FFMA2 compute) --------
__device__ __forceinline__ float fast_sigmoid(float v) {
    return 1.f / (1.f + __expf(-v));
}
__device__ __forceinline__ float fast_tanh(float v) {
    v = fminf(fmaxf(v, -15.f), 15.f);
    float e = __expf(-2.f * v);
    return (1.f - e) / (1.f + e);
}

__global__ __launch_bounds__(256, 1) void recur_kernel() {
    __shared__ __align__(16) float h_s[HDIM];
    const int tid  = threadIdx.x;
    const int lane = tid & 31;
    const int warp = tid >> 5;                 // 0..7
    const int j    = blockIdx.x * 8 + warp;    // h element, 0..1023

    // This warp's 4 gate rows of W_comb in registers, packed f32x2.
    // Lane handles col pairs {p*64 + 2*lane, +1}, p = 0..15. (R4-proven.)
    u64 w2[4][16];
#pragma unroll
    for (int g = 0; g < 4; g++) {
        const u64* base = (const u64*)(g_Wcomb + (size_t)(j + g * HDIM) * HDIM);
#pragma unroll
        for (int p = 0; p < 16; p++) w2[g][p] = base[p * 32 + lane];
    }

    float c_state = 0.f;    // meaningful on lane 0 only

    for (int t = 0; t < LSEQ; t++) {
        // Gate pre-activations from pregemm (R6: blocking poll, nanosleep 64).
        float xi = 0.f, xf = 0.f, xg = 0.f, xo = 0.f;
        if (lane == 0) {
            const float* xp = g_Xpre + (size_t)t * G4;
            xi = poll_scalar(xp + j);
            xf = poll_scalar(xp + j + 1024);
            xg = poll_scalar(xp + j + 2048);
            xo = poll_scalar(xp + j + 3072);
        }

        // Stage h_{t-1}: poll the values themselves until non-sentinel.
        if (t == 0) {
            ((float4*)h_s)[tid] = make_float4(0.f, 0.f, 0.f, 0.f);
        } else {
            const float4* hp4 = (const float4*)(g_outs + (size_t)(t - 1) * HDIM);
            float4 v = ldcg4(hp4 + tid);
            while (has_sentinel(v)) {
                __nanosleep(64);
                v = ldcg4(hp4 + tid);
            }
            ((float4*)h_s)[tid] = v;
        }
        __syncthreads();

        u64 acc0 = pack2(0.f, 0.f), acc1 = acc0, acc2v = acc0, acc3 = acc0;
        const u64* h2 = (const u64*)h_s;
#pragma unroll
        for (int p = 0; p < 16; p++) {
            u64 hv = h2[p * 32 + lane];
            acc0  = fma2(w2[0][p], hv, acc0);
            acc1  = fma2(w2[1][p], hv, acc1);
            acc2v = fma2(w2[2][p], hv, acc2v);
            acc3  = fma2(w2[3][p], hv, acc3);
        }
        float l0, h0, l1, h1, l2, hh2, l3, h3;
        unpack2(acc0, l0, h0);
        unpack2(acc1, l1, h1);
        unpack2(acc2v, l2, hh2);
        unpack2(acc3, l3, h3);
        float a0 = l0 + h0, a1 = l1 + h1, a2 = l2 + hh2, a3 = l3 + h3;
#pragma unroll
        for (int off = 16; off > 0; off >>= 1) {
            a0 += __shfl_down_sync(0xffffffffu, a0, off);
            a1 += __shfl_down_sync(0xffffffffu, a1, off);
            a2 += __shfl_down_sync(0xffffffffu, a2, off);
            a3 += __shfl_down_sync(0xffffffffu, a3, off);
        }
        if (lane == 0) {
            float gi = xi + a0;
            float gf = xf + a1;
            float gg = xg + a2;
            float go = xo + a3;
            float si = fast_sigmoid(gi);
            float sf = fast_sigmoid(gf);
            float so = fast_sigmoid(go);
            c_state = sf * c_state + si * fast_tanh(gg);
            // This store is the release: consumers poll this exact location.
            stcg(g_outs + (size_t)t * HDIM + j, so * fast_tanh(c_state));
        }
        __syncthreads();   // protect h_s reuse next iteration
    }
}

// ---------------- final FC: out[t][l] = b_fc[l] + outs[t] . W_fc[l] ----------
__global__ __launch_bounds__(256) void fc_kernel(const float* __restrict__ W_fc,
                                                 const float* __restrict__ b_fc,
                                                 float* __restrict__ out) {
    __shared__ __align__(16) float hs[4][HDIM];
    const int t0  = blockIdx.x * 4;
    const int tid = threadIdx.x;
    const int half = tid >> 7;          // 0 or 1
    const int l    = tid & 127;         // label index

    const float4* src = (const float4*)(g_outs + (size_t)t0 * HDIM);
    float4* dst = (float4*)hs;
#pragma unroll
    for (int i = tid; i < HDIM; i += 256) dst[i] = src[i];   // 1024 float4
    __syncthreads();

    if (l < NLAB) {
        const float4* wr = (const float4*)(W_fc + (size_t)l * HDIM);
        const float4* ha = (const float4*)hs[half * 2];
        const float4* hb = (const float4*)hs[half * 2 + 1];
        float s0 = 0.f, s1 = 0.f;
#pragma unroll 8
        for (int k = 0; k < HDIM / 4; k++) {
            float4 w = wr[k];
            float4 a = ha[k], b = hb[k];
            s0 += w.x * a.x + w.y * a.y + w.z * a.z + w.w * a.w;
            s1 += w.x * b.x + w.y * b.y + w.z * b.z + w.w * b.w;
        }
        float bb = b_fc[l];
        out[(size_t)(t0 + half * 2) * NLAB + l]     = s0 + bb;
        out[(size_t)(t0 + half * 2 + 1) * NLAB + l] = s1 + bb;
    }
}

// ---------------- launch (R6 ordering: dependency-free pregemm first) ---------
extern "C" void kernel_launch(void* const* d_in, const int* in_sizes, int n_in,
                              void* d_out, int out_size) {
    const float* x    = (const float*)d_in[0];
    const float* hi   = (const float*)d_in[1];
    const float* W_ih = (const float*)d_in[2];
    const float* W_hh = (const float*)d_in[3];
    const float* b_ih = (const float*)d_in[4];
    const float* b_hh = (const float*)d_in[5];
    const float* W_fc = (const float*)d_in[6];
    const float* b_fc = (const float*)d_in[7];
    float* out = (float*)d_out;

    static cudaStream_t s2 = nullptr;
    static cudaEvent_t evA = nullptr, evB = nullptr;
    if (s2 == nullptr) {
        cudaStreamCreateWithFlags(&s2, cudaStreamNonBlocking);
        cudaEventCreateWithFlags(&evA, cudaEventDisableTiming);
        cudaEventCreateWithFlags(&evB, cudaEventDisableTiming);
    }

    prep_kernel<<<(G4 * HDIM + 255) / 256, 256>>>(W_ih, W_hh, b_ih, b_hh);

    // Fork after prep: pregemm on s2 (never waits on anything), then recur.
    cudaEventRecord(evA, 0);
    cudaStreamWaitEvent(s2, evA, 0);

    dim3 pgrid(64, 8);   // 64 n-strips x 8 t-blocks
    pregemm_kernel<<<pgrid, 128, 0, s2>>>(x, hi, W_ih);
    cudaEventRecord(evB, s2);

    recur_kernel<<<RGRID, 256>>>();

    // Join before fc (fc reads g_outs; graph re-converges here).
    cudaStreamWaitEvent(0, evB, 0);
    fc_kernel<<<LSEQ / 4, 256>>>(W_fc, b_fc, out);
}

// round 15
// speedup vs baseline: 2.1391x; 1.0238x over previous
#include <cuda_runtime.h>

#define HDIM 1024
#define LSEQ 512
#define G4   4096      // 4*H gate rows
#define KIN  4096      // input feature dim (2H + 2H)
#define NLAB 122
#define RGRID 128      // recurrent kernel CTAs (<=148: one wave, persistent-safe)

#define SENTINEL 0x7FC00001u   // NaN payload; computed values are never NaN

// ---------------- scratch (no allocation allowed; device globals) -------------
__device__ __align__(256) float g_Wcomb[G4 * HDIM];   // W_ih[:,4096:] + W_hh
__device__ __align__(256) float g_bias[G4];           // b_ih + b_hh
__device__ __align__(256) float g_Xpre[LSEQ * G4];    // input projection + bias
__device__ __align__(256) float g_outs[LSEQ * HDIM];  // h_t for all steps

// ---------------- L2-coherent load/store helpers ------------------------------
__device__ __forceinline__ float4 ldcg4(const float4* p) {
    float4 v;
    asm volatile("ld.global.cg.v4.f32 {%0,%1,%2,%3}, [%4];"
                 : "=f"(v.x), "=f"(v.y), "=f"(v.z), "=f"(v.w) : "l"(p));
    return v;
}
__device__ __forceinline__ float ldcg1(const float* p) {
    float v;
    asm volatile("ld.global.cg.f32 %0, [%1];" : "=f"(v) : "l"(p));
    return v;
}
__device__ __forceinline__ void stcg(float* p, float v) {
    asm volatile("st.global.cg.f32 [%0], %1;" :: "l"(p), "f"(v));
}
__device__ __forceinline__ bool has_sentinel(float4 v) {
    return (__float_as_uint(v.x) == SENTINEL) | (__float_as_uint(v.y) == SENTINEL) |
           (__float_as_uint(v.z) == SENTINEL) | (__float_as_uint(v.w) == SENTINEL);
}
// Cycle-granular pause: replaces __nanosleep's coarse quantum (the ONE change
// vs the R6 baseline). ~80 cycles keeps poll traffic throttled without
// charging a ~microsecond quantum to every step's first failed poll.
__device__ __forceinline__ void pause80() {
    unsigned long long s = clock64();
    while (clock64() - s < 80ull) { }
}
__device__ __forceinline__ float poll_scalar(const float* p) {
    float v = ldcg1(p);
    while (__float_as_uint(v) == SENTINEL) { pause80(); v = ldcg1(p); }
    return v;
}

// ---------------- prep: fold weights/biases, poison Xpre + h buffers ----------
__global__ void prep_kernel(const float* __restrict__ W_ih,
                            const float* __restrict__ W_hh,
                            const float* __restrict__ b_ih,
                            const float* __restrict__ b_hh) {
    int idx = blockIdx.x * blockDim.x + threadIdx.x;
    if (idx < G4 * HDIM) {
        int r = idx >> 10;           // gate row
        int c = idx & 1023;          // h col
        g_Wcomb[idx] = W_ih[(size_t)r * 5120 + 4096 + c] + W_hh[idx];
    }
    if (idx < G4) g_bias[idx] = b_ih[idx] + b_hh[idx];
    if (idx < LSEQ * G4)  g_Xpre[idx] = __uint_as_float(SENTINEL);
    if (idx < LSEQ * HDIM) g_outs[idx] = __uint_as_float(SENTINEL);
}

// ---------------- pregemm: 64x64x16 tiles, 512 slim CTAs (R6 config) ----------
__global__ __launch_bounds__(128) void pregemm_kernel(
    const float* __restrict__ x, const float* __restrict__ hi,
    const float* __restrict__ W_ih) {
    __shared__ __align__(16) float As[16][68];   // [k][t]
    __shared__ __align__(16) float Bs[16][68];   // [k][n]

    const int bn = blockIdx.x * 64;   // gate-row strip
    const int bt = blockIdx.y * 64;   // timestep block
    const int tid = threadIdx.x;
    const int tm = tid & 15;          // 16 m-groups of 4 rows
    const int tn = tid >> 4;          // 8 n-groups of 8 cols

    float acc[4][8];
#pragma unroll
    for (int i = 0; i < 4; i++)
#pragma unroll
        for (int j = 0; j < 8; j++) acc[i][j] = 0.f;

    for (int k0 = 0; k0 < KIN; k0 += 16) {
        // A tile: 64 t-rows x 16 k = 256 float4, 128 thr -> 2 each.
        // float4 never straddles the x/hi boundary (2048 % 16 == 0).
#pragma unroll
        for (int it = 0; it < 2; it++) {
            int idx = tid + it * 128;
            int m = idx >> 2;
            int kq = idx & 3;
            int gk = k0 + kq * 4;
            float4 v;
            if (gk < 2048)
                v = *(const float4*)(x + (size_t)(bt + m) * 2048 + gk);
            else
                v = *(const float4*)(hi + (size_t)(bt + m) * 2048 + gk - 2048);
            As[kq * 4 + 0][m] = v.x;
            As[kq * 4 + 1][m] = v.y;
            As[kq * 4 + 2][m] = v.z;
            As[kq * 4 + 3][m] = v.w;
        }
        // B tile: 64 gate rows x 16 k (W_ih row stride 5120 floats)
#pragma unroll
        for (int it = 0; it < 2; it++) {
            int idx = tid + it * 128;
            int n = idx >> 2;
            int kq = idx & 3;
            float4 v = *(const float4*)(W_ih + (size_t)(bn + n) * 5120 + k0 + kq * 4);
            Bs[kq * 4 + 0][n] = v.x;
            Bs[kq * 4 + 1][n] = v.y;
            Bs[kq * 4 + 2][n] = v.z;
            Bs[kq * 4 + 3][n] = v.w;
        }
        __syncthreads();
#pragma unroll
        for (int k = 0; k < 16; k++) {
            float4 a4 = *(const float4*)&As[k][tm * 4];
            float4 b0 = *(const float4*)&Bs[k][tn * 8];
            float4 b1 = *(const float4*)&Bs[k][tn * 8 + 4];
            float a[4] = {a4.x, a4.y, a4.z, a4.w};
            float b[8] = {b0.x, b0.y, b0.z, b0.w, b1.x, b1.y, b1.z, b1.w};
#pragma unroll
            for (int i = 0; i < 4; i++)
#pragma unroll
                for (int j = 0; j < 8; j++) acc[i][j] += a[i] * b[j];
        }
        __syncthreads();
    }
    // Epilogue: add bias, st.cg so polling recur CTAs see values in L2.
#pragma unroll
    for (int j = 0; j < 8; j++) {
        int n = bn + tn * 8 + j;
        float bb = g_bias[n];
#pragma unroll
        for (int i = 0; i < 4; i++) {
            int m = bt + tm * 4 + i;
            stcg(g_Xpre + (size_t)m * G4 + n, acc[i][j] + bb);
        }
    }
}

// ---------------- recurrent persistent kernel (R6 structure) ------------------
__device__ __forceinline__ float fast_sigmoid(float v) {
    return 1.f / (1.f + __expf(-v));
}
__device__ __forceinline__ float fast_tanh(float v) {
    v = fminf(fmaxf(v, -15.f), 15.f);
    float e = __expf(-2.f * v);
    return (1.f - e) / (1.f + e);
}

__global__ __launch_bounds__(256, 1) void recur_kernel() {
    __shared__ __align__(16) float h_s[HDIM];
    const int tid  = threadIdx.x;
    const int lane = tid & 31;
    const int warp = tid >> 5;                 // 0..7
    const int j    = blockIdx.x * 8 + warp;    // h element, 0..1023

    // This warp's 4 gate rows of W_comb live in registers.
    // Lane handles cols {lane, lane+32, ..., lane+992}.
    float w[4][32];
#pragma unroll
    for (int g = 0; g < 4; g++) {
        const float* base = g_Wcomb + (size_t)(j + g * HDIM) * HDIM;
#pragma unroll
        for (int k = 0; k < 32; k++) w[g][k] = base[k * 32 + lane];
    }

    float c_state = 0.f;    // meaningful on lane 0 only

    for (int t = 0; t < LSEQ; t++) {
        // Gate pre-activations from pregemm (blocking poll, cycle pause).
        float xi = 0.f, xf = 0.f, xg = 0.f, xo = 0.f;
        if (lane == 0) {
            const float* xp = g_Xpre + (size_t)t * G4;
            xi = poll_scalar(xp + j);
            xf = poll_scalar(xp + j + 1024);
            xg = poll_scalar(xp + j + 2048);
            xo = poll_scalar(xp + j + 3072);
        }

        // Stage h_{t-1}: poll the values themselves until non-sentinel.
        if (t == 0) {
            ((float4*)h_s)[tid] = make_float4(0.f, 0.f, 0.f, 0.f);
        } else {
            const float4* hp4 = (const float4*)(g_outs + (size_t)(t - 1) * HDIM);
            float4 v = ldcg4(hp4 + tid);
            while (has_sentinel(v)) {
                pause80();
                v = ldcg4(hp4 + tid);
            }
            ((float4*)h_s)[tid] = v;
        }
        __syncthreads();

        float a0 = 0.f, a1 = 0.f, a2 = 0.f, a3 = 0.f;
#pragma unroll
        for (int k = 0; k < 32; k++) {
            float hv = h_s[k * 32 + lane];
            a0 += w[0][k] * hv;
            a1 += w[1][k] * hv;
            a2 += w[2][k] * hv;
            a3 += w[3][k] * hv;
        }
#pragma unroll
        for (int off = 16; off > 0; off >>= 1) {
            a0 += __shfl_down_sync(0xffffffffu, a0, off);
            a1 += __shfl_down_sync(0xffffffffu, a1, off);
            a2 += __shfl_down_sync(0xffffffffu, a2, off);
            a3 += __shfl_down_sync(0xffffffffu, a3, off);
        }
        if (lane == 0) {
            float gi = xi + a0;
            float gf = xf + a1;
            float gg = xg + a2;
            float go = xo + a3;
            float si = fast_sigmoid(gi);
            float sf = fast_sigmoid(gf);
            float so = fast_sigmoid(go);
            c_state = sf * c_state + si * fast_tanh(gg);
            // This store is the release: consumers poll this exact location.
            stcg(g_outs + (size_t)t * HDIM + j, so * fast_tanh(c_state));
        }
        __syncthreads();   // protect h_s reuse next iteration
    }
}

// ---------------- final FC: out[t][l] = b_fc[l] + outs[t] . W_fc[l] ----------
__global__ __launch_bounds__(256) void fc_kernel(const float* __restrict__ W_fc,
                                                 const float* __restrict__ b_fc,
                                                 float* __restrict__ out) {
    __shared__ __align__(16) float hs[4][HDIM];
    const int t0  = blockIdx.x * 4;
    const int tid = threadIdx.x;
    const int half = tid >> 7;          // 0 or 1
    const int l    = tid & 127;         // label index

    const float4* src = (const float4*)(g_outs + (size_t)t0 * HDIM);
    float4* dst = (float4*)hs;
#pragma unroll
    for (int i = tid; i < HDIM; i += 256) dst[i] = src[i];   // 1024 float4
    __syncthreads();

    if (l < NLAB) {
        const float4* wr = (const float4*)(W_fc + (size_t)l * HDIM);
        const float4* ha = (const float4*)hs[half * 2];
        const float4* hb = (const float4*)hs[half * 2 + 1];
        float s0 = 0.f, s1 = 0.f;
#pragma unroll 8
        for (int k = 0; k < HDIM / 4; k++) {
            float4 w = wr[k];
            float4 a = ha[k], b = hb[k];
            s0 += w.x * a.x + w.y * a.y + w.z * a.z + w.w * a.w;
            s1 += w.x * b.x + w.y * b.y + w.z * b.z + w.w * b.w;
        }
        float bb = b_fc[l];
        out[(size_t)(t0 + half * 2) * NLAB + l]     = s0 + bb;
        out[(size_t)(t0 + half * 2 + 1) * NLAB + l] = s1 + bb;
    }
}

// ---------------- launch (R6 ordering: dependency-free pregemm first) ---------
extern "C" void kernel_launch(void* const* d_in, const int* in_sizes, int n_in,
                              void* d_out, int out_size) {
    const float* x    = (const float*)d_in[0];
    const float* hi   = (const float*)d_in[1];
    const float* W_ih = (const float*)d_in[2];
    const float* W_hh = (const float*)d_in[3];
    const float* b_ih = (const float*)d_in[4];
    const float* b_hh = (const float*)d_in[5];
    const float* W_fc = (const float*)d_in[6];
    const float* b_fc = (const float*)d_in[7];
    float* out = (float*)d_out;

    static cudaStream_t s2 = nullptr;
    static cudaEvent_t evA = nullptr, evB = nullptr;
    if (s2 == nullptr) {
        cudaStreamCreateWithFlags(&s2, cudaStreamNonBlocking);
        cudaEventCreateWithFlags(&evA, cudaEventDisableTiming);
        cudaEventCreateWithFlags(&evB, cudaEventDisableTiming);
    }

    prep_kernel<<<(G4 * HDIM + 255) / 256, 256>>>(W_ih, W_hh, b_ih, b_hh);

    // Fork after prep: pregemm on s2 (never waits on anything), then recur.
    cudaEventRecord(evA, 0);
    cudaStreamWaitEvent(s2, evA, 0);

    dim3 pgrid(64, 8);   // 64 n-strips x 8 t-blocks
    pregemm_kernel<<<pgrid, 128, 0, s2>>>(x, hi, W_ih);
    cudaEventRecord(evB, s2);

    recur_kernel<<<RGRID, 256>>>();

    // Join before fc (fc reads g_outs; graph re-converges here).
    cudaStreamWaitEvent(0, evB, 0);
    fc_kernel<<<LSEQ / 4, 256>>>(W_fc, b_fc, out);
}

// round 16
// speedup vs baseline: 2.1599x; 1.0097x over previous
#include <cuda_runtime.h>

#define HDIM 1024
#define LSEQ 512
#define G4   4096      // 4*H gate rows
#define KIN  4096      // input feature dim (2H + 2H)
#define NLAB 122
#define RGRID 128      // recurrent kernel CTAs (<=148: one wave, persistent-safe)

#define SENTINEL 0x7FC00001u   // NaN payload; computed values are never NaN

typedef unsigned long long u64;

// ---------------- packed f32x2 helpers (FFMA2, pregemm only) ------------------
__device__ __forceinline__ u64 pack2(float lo, float hi) {
    u64 r; asm("mov.b64 %0, {%1, %2};" : "=l"(r) : "f"(lo), "f"(hi)); return r;
}
__device__ __forceinline__ void unpack2(u64 v, float& lo, float& hi) {
    asm("mov.b64 {%0, %1}, %2;" : "=f"(lo), "=f"(hi) : "l"(v));
}
__device__ __forceinline__ u64 fma2(u64 a, u64 b, u64 c) {
    u64 d; asm("fma.rn.f32x2 %0, %1, %2, %3;" : "=l"(d) : "l"(a), "l"(b), "l"(c));
    return d;
}

// ---------------- scratch (no allocation allowed; device globals) -------------
__device__ __align__(256) float g_Wcomb[G4 * HDIM];   // W_ih[:,4096:] + W_hh
__device__ __align__(256) float g_bias[G4];           // b_ih + b_hh
__device__ __align__(256) float g_Xpre[LSEQ * G4];    // input projection + bias
__device__ __align__(256) float g_outs[LSEQ * HDIM];  // h_t for all steps

// ---------------- L2-coherent load/store helpers (R6-proven) ------------------
__device__ __forceinline__ float4 ldcg4(const float4* p) {
    float4 v;
    asm volatile("ld.global.cg.v4.f32 {%0,%1,%2,%3}, [%4];"
                 : "=f"(v.x), "=f"(v.y), "=f"(v.z), "=f"(v.w) : "l"(p));
    return v;
}
__device__ __forceinline__ float ldcg1(const float* p) {
    float v;
    asm volatile("ld.global.cg.f32 %0, [%1];" : "=f"(v) : "l"(p));
    return v;
}
__device__ __forceinline__ void stcg(float* p, float v) {
    asm volatile("st.global.cg.f32 [%0], %1;" :: "l"(p), "f"(v));
}
__device__ __forceinline__ bool has_sentinel(float4 v) {
    return (__float_as_uint(v.x) == SENTINEL) | (__float_as_uint(v.y) == SENTINEL) |
           (__float_as_uint(v.z) == SENTINEL) | (__float_as_uint(v.w) == SENTINEL);
}
__device__ __forceinline__ float poll_scalar(const float* p) {
    float v = ldcg1(p);
    while (__float_as_uint(v) == SENTINEL) { __nanosleep(64); v = ldcg1(p); }
    return v;
}

// ---------------- prep: fold weights/biases, poison Xpre + h buffers ----------
__global__ void prep_kernel(const float* __restrict__ W_ih,
                            const float* __restrict__ W_hh,
                            const float* __restrict__ b_ih,
                            const float* __restrict__ b_hh) {
    int idx = blockIdx.x * blockDim.x + threadIdx.x;
    if (idx < G4 * HDIM) {
        int r = idx >> 10;           // gate row
        int c = idx & 1023;          // h col
        g_Wcomb[idx] = W_ih[(size_t)r * 5120 + 4096 + c] + W_hh[idx];
    }
    if (idx < G4) g_bias[idx] = b_ih[idx] + b_hh[idx];
    if (idx < LSEQ * G4)  g_Xpre[idx] = __uint_as_float(SENTINEL);
    if (idx < LSEQ * HDIM) g_outs[idx] = __uint_as_float(SENTINEL);
}

// ---------------- pregemm: 64x64x16 tiles, 512 slim CTAs, FFMA2 inner loop ----
// FMA-pipe-bound at ~86% of the scalar FFMA ceiling; f32x2 doubles the
// ceiling (2 FLOP/issue, same rt). Numerics R4/R14-proven: per-output
// accumulation order unchanged (packing is across the m dimension).
__global__ __launch_bounds__(128) void pregemm_kernel(
    const float* __restrict__ x, const float* __restrict__ hi,
    const float* __restrict__ W_ih) {
    __shared__ __align__(16) float As[16][68];   // [k][t]
    __shared__ __align__(16) float Bs[16][68];   // [k][n]

    const int bn = blockIdx.x * 64;   // gate-row strip
    const int bt = blockIdx.y * 64;   // timestep block
    const int tid = threadIdx.x;
    const int tm = tid & 15;          // 16 m-groups of 4 rows
    const int tn = tid >> 4;          // 8 n-groups of 8 cols

    u64 acc2[2][8];                    // packed over m (4 rows -> 2 pairs)
#pragma unroll
    for (int i = 0; i < 2; i++)
#pragma unroll
        for (int j = 0; j < 8; j++) acc2[i][j] = pack2(0.f, 0.f);

    for (int k0 = 0; k0 < KIN; k0 += 16) {
        // A tile: 64 t-rows x 16 k = 256 float4, 128 thr -> 2 each.
        // float4 never straddles the x/hi boundary (2048 % 16 == 0).
#pragma unroll
        for (int it = 0; it < 2; it++) {
            int idx = tid + it * 128;
            int m = idx >> 2;
            int kq = idx & 3;
            int gk = k0 + kq * 4;
            float4 v;
            if (gk < 2048)
                v = *(const float4*)(x + (size_t)(bt + m) * 2048 + gk);
            else
                v = *(const float4*)(hi + (size_t)(bt + m) * 2048 + gk - 2048);
            As[kq * 4 + 0][m] = v.x;
            As[kq * 4 + 1][m] = v.y;
            As[kq * 4 + 2][m] = v.z;
            As[kq * 4 + 3][m] = v.w;
        }
        // B tile: 64 gate rows x 16 k (W_ih row stride 5120 floats)
#pragma unroll
        for (int it = 0; it < 2; it++) {
            int idx = tid + it * 128;
            int n = idx >> 2;
            int kq = idx & 3;
            float4 v = *(const float4*)(W_ih + (size_t)(bn + n) * 5120 + k0 + kq * 4);
            Bs[kq * 4 + 0][n] = v.x;
            Bs[kq * 4 + 1][n] = v.y;
            Bs[kq * 4 + 2][n] = v.z;
            Bs[kq * 4 + 3][n] = v.w;
        }
        __syncthreads();
#pragma unroll
        for (int k = 0; k < 16; k++) {
            u64 a2[2];
            a2[0] = *(const u64*)&As[k][tm * 4];
            a2[1] = *(const u64*)&As[k][tm * 4 + 2];
            u64 b2[8];
#pragma unroll
            for (int j = 0; j < 8; j++) {
                float bv = Bs[k][tn * 8 + j];
                b2[j] = pack2(bv, bv);
            }
#pragma unroll
            for (int i = 0; i < 2; i++)
#pragma unroll
                for (int j = 0; j < 8; j++)
                    acc2[i][j] = fma2(a2[i], b2[j], acc2[i][j]);
        }
        __syncthreads();
    }
    // Epilogue: add bias; st.cg so polling recur CTAs see values in L2.
#pragma unroll
    for (int i = 0; i < 2; i++) {
#pragma unroll
        for (int j = 0; j < 8; j++) {
            int n = bn + tn * 8 + j;
            float lo, hh;
            unpack2(acc2[i][j], lo, hh);
            int m0 = bt + tm * 4 + 2 * i;
            float bb = g_bias[n];
            stcg(g_Xpre + (size_t)m0 * G4 + n,       lo + bb);
            stcg(g_Xpre + (size_t)(m0 + 1) * G4 + n, hh + bb);
        }
    }
}

// ---------------- recurrent persistent kernel (EXACT R6: scalar FMA) ----------
__device__ __forceinline__ float fast_sigmoid(float v) {
    return 1.f / (1.f + __expf(-v));
}
__device__ __forceinline__ float fast_tanh(float v) {
    v = fminf(fmaxf(v, -15.f), 15.f);
    float e = __expf(-2.f * v);
    return (1.f - e) / (1.f + e);
}

__global__ __launch_bounds__(256, 1) void recur_kernel() {
    __shared__ __align__(16) float h_s[HDIM];
    const int tid  = threadIdx.x;
    const int lane = tid & 31;
    const int warp = tid >> 5;                 // 0..7
    const int j    = blockIdx.x * 8 + warp;    // h element, 0..1023

    // This warp's 4 gate rows of W_comb live in registers (scalar — the
    // u64-packed variant costs ~+300us from register pressure; R14).
    float w[4][32];
#pragma unroll
    for (int g = 0; g < 4; g++) {
        const float* base = g_Wcomb + (size_t)(j + g * HDIM) * HDIM;
#pragma unroll
        for (int k = 0; k < 32; k++) w[g][k] = base[k * 32 + lane];
    }

    float c_state = 0.f;    // meaningful on lane 0 only

    for (int t = 0; t < LSEQ; t++) {
        // Gate pre-activations from pregemm (blocking poll, nanosleep 64).
        float xi = 0.f, xf = 0.f, xg = 0.f, xo = 0.f;
        if (lane == 0) {
            const float* xp = g_Xpre + (size_t)t * G4;
            xi = poll_scalar(xp + j);
            xf = poll_scalar(xp + j + 1024);
            xg = poll_scalar(xp + j + 2048);
            xo = poll_scalar(xp + j + 3072);
        }

        // Stage h_{t-1}: poll the values themselves until non-sentinel.
        if (t == 0) {
            ((float4*)h_s)[tid] = make_float4(0.f, 0.f, 0.f, 0.f);
        } else {
            const float4* hp4 = (const float4*)(g_outs + (size_t)(t - 1) * HDIM);
            float4 v = ldcg4(hp4 + tid);
            while (has_sentinel(v)) {
                __nanosleep(64);
                v = ldcg4(hp4 + tid);
            }
            ((float4*)h_s)[tid] = v;
        }
        __syncthreads();

        float a0 = 0.f, a1 = 0.f, a2 = 0.f, a3 = 0.f;
#pragma unroll
        for (int k = 0; k < 32; k++) {
            float hv = h_s[k * 32 + lane];
            a0 += w[0][k] * hv;
            a1 += w[1][k] * hv;
            a2 += w[2][k] * hv;
            a3 += w[3][k] * hv;
        }
#pragma unroll
        for (int off = 16; off > 0; off >>= 1) {
            a0 += __shfl_down_sync(0xffffffffu, a0, off);
            a1 += __shfl_down_sync(0xffffffffu, a1, off);
            a2 += __shfl_down_sync(0xffffffffu, a2, off);
            a3 += __shfl_down_sync(0xffffffffu, a3, off);
        }
        if (lane == 0) {
            float gi = xi + a0;
            float gf = xf + a1;
            float gg = xg + a2;
            float go = xo + a3;
            float si = fast_sigmoid(gi);
            float sf = fast_sigmoid(gf);
            float so = fast_sigmoid(go);
            c_state = sf * c_state + si * fast_tanh(gg);
            // This store is the release: consumers poll this exact location.
            stcg(g_outs + (size_t)t * HDIM + j, so * fast_tanh(c_state));
        }
        __syncthreads();   // protect h_s reuse next iteration
    }
}

// ---------------- final FC: out[t][l] = b_fc[l] + outs[t] . W_fc[l] ----------
__global__ __launch_bounds__(256) void fc_kernel(const float* __restrict__ W_fc,
                                                 const float* __restrict__ b_fc,
                                                 float* __restrict__ out) {
    __shared__ __align__(16) float hs[4][HDIM];
    const int t0  = blockIdx.x * 4;
    const int tid = threadIdx.x;
    const int half = tid >> 7;          // 0 or 1
    const int l    = tid & 127;         // label index

    const float4* src = (const float4*)(g_outs + (size_t)t0 * HDIM);
    float4* dst = (float4*)hs;
#pragma unroll
    for (int i = tid; i < HDIM; i += 256) dst[i] = src[i];   // 1024 float4
    __syncthreads();

    if (l < NLAB) {
        const float4* wr = (const float4*)(W_fc + (size_t)l * HDIM);
        const float4* ha = (const float4*)hs[half * 2];
        const float4* hb = (const float4*)hs[half * 2 + 1];
        float s0 = 0.f, s1 = 0.f;
#pragma unroll 8
        for (int k = 0; k < HDIM / 4; k++) {
            float4 w = wr[k];
            float4 a = ha[k], b = hb[k];
            s0 += w.x * a.x + w.y * a.y + w.z * a.z + w.w * a.w;
            s1 += w.x * b.x + w.y * b.y + w.z * b.z + w.w * b.w;
        }
        float bb = b_fc[l];
        out[(size_t)(t0 + half * 2) * NLAB + l]     = s0 + bb;
        out[(size_t)(t0 + half * 2 + 1) * NLAB + l] = s1 + bb;
    }
}

// ---------------- launch (R6 ordering: dependency-free pregemm first) ---------
extern "C" void kernel_launch(void* const* d_in, const int* in_sizes, int n_in,
                              void* d_out, int out_size) {
    const float* x    = (const float*)d_in[0];
    const float* hi   = (const float*)d_in[1];
    const float* W_ih = (const float*)d_in[2];
    const float* W_hh = (const float*)d_in[3];
    const float* b_ih = (const float*)d_in[4];
    const float* b_hh = (const float*)d_in[5];
    const float* W_fc = (const float*)d_in[6];
    const float* b_fc = (const float*)d_in[7];
    float* out = (float*)d_out;

    static cudaStream_t s2 = nullptr;
    static cudaEvent_t evA = nullptr, evB = nullptr;
    if (s2 == nullptr) {
        cudaStreamCreateWithFlags(&s2, cudaStreamNonBlocking);
        cudaEventCreateWithFlags(&evA, cudaEventDisableTiming);
        cudaEventCreateWithFlags(&evB, cudaEventDisableTiming);
    }

    prep_kernel<<<(G4 * HDIM + 255) / 256, 256>>>(W_ih, W_hh, b_ih, b_hh);

    // Fork after prep: pregemm on s2 (never waits on anything), then recur.
    cudaEventRecord(evA, 0);
    cudaStreamWaitEvent(s2, evA, 0);

    dim3 pgrid(64, 8);   // 64 n-strips x 8 t-blocks
    pregemm_kernel<<<pgrid, 128, 0, s2>>>(x, hi, W_ih);
    cudaEventRecord(evB, s2);

    recur_kernel<<<RGRID, 256>>>();

    // Join before fc (fc reads g_outs; graph re-converges here).
    cudaStreamWaitEvent(0, evB, 0);
    fc_kernel<<<LSEQ / 4, 256>>>(W_fc, b_fc, out);
}